// round 13
// baseline (speedup 1.0000x reference)
#include <cuda_runtime.h>
#include <cuda_fp16.h>
#include <math.h>
#include <stdint.h>

// Problem constants
#define N_B   4
#define T_S   2048
#define D_M   1024
#define H_N   16
#define DH    64
#define MROWS (N_B * T_S)   // 8192
#define GK    1024          // GEMM K

// ---------------------------------------------------------------------------
// Scratch (alloc-free rule: __device__ globals) — all f16
// ---------------------------------------------------------------------------
__device__ __half g_qh  [(size_t)MROWS * D_M];
__device__ __half g_Qh  [(size_t)MROWS * D_M];
__device__ __half g_Kh  [(size_t)MROWS * D_M];
__device__ __half g_Vh  [(size_t)MROWS * D_M];
__device__ __half g_ctxh[(size_t)MROWS * D_M];
__device__ __half g_Wqh [(size_t)D_M * D_M];
__device__ __half g_Wkh [(size_t)D_M * D_M];
__device__ __half g_Wvh [(size_t)D_M * D_M];
__device__ __half g_Woh [(size_t)D_M * D_M];

// ---------------------------------------------------------------------------
// Helpers (sm_100 plain target: NO tcgen05)
// ---------------------------------------------------------------------------
__device__ __forceinline__ uint32_t smem_to_u32(const void* p) {
    uint32_t a;
    asm("{ .reg .u64 t; cvta.to.shared.u64 t, %1; cvt.u32.u64 %0, t; }"
        : "=r"(a) : "l"(p));
    return a;
}
__device__ __forceinline__ void cpa16(uint32_t dst, const void* src) {
    asm volatile("cp.async.cg.shared.global [%0], [%1], 16;"
                 :: "r"(dst), "l"(src) : "memory");
}
#define CP_COMMIT() asm volatile("cp.async.commit_group;" ::: "memory")

__device__ __forceinline__ uint32_t packh2(float lo, float hi) {
    __half2 h = __floats2half2_rn(lo, hi);
    return *(uint32_t*)&h;
}
// D(16x8,f32) += A(16x16,f16 row) * B(16x8,f16 col)
__device__ __forceinline__ void mma_f16(float* d, const uint32_t* a,
                                        uint32_t b0, uint32_t b1) {
    asm volatile(
        "mma.sync.aligned.m16n8k16.row.col.f32.f16.f16.f32 "
        "{%0,%1,%2,%3}, {%4,%5,%6,%7}, {%8,%9}, {%0,%1,%2,%3};"
        : "+f"(d[0]), "+f"(d[1]), "+f"(d[2]), "+f"(d[3])
        : "r"(a[0]), "r"(a[1]), "r"(a[2]), "r"(a[3]),
          "r"(b0), "r"(b1));
}
__device__ __forceinline__ void ldsm_x2(uint32_t addr, uint32_t& r0, uint32_t& r1) {
    asm volatile("ldmatrix.sync.aligned.m8n8.x2.shared.b16 {%0,%1}, [%2];"
                 : "=r"(r0), "=r"(r1) : "r"(addr));
}
__device__ __forceinline__ void ldsm_x2t(uint32_t addr, uint32_t& r0, uint32_t& r1) {
    asm volatile("ldmatrix.sync.aligned.m8n8.x2.trans.shared.b16 {%0,%1}, [%2];"
                 : "=r"(r0), "=r"(r1) : "r"(addr));
}
__device__ __forceinline__ void ldsm_x4(uint32_t addr, uint32_t* r) {
    asm volatile("ldmatrix.sync.aligned.m8n8.x4.shared.b16 {%0,%1,%2,%3}, [%4];"
                 : "=r"(r[0]), "=r"(r[1]), "=r"(r[2]), "=r"(r[3]) : "r"(addr));
}

// ---------------------------------------------------------------------------
// fp32 -> fp16 converts: one launch for query, one for all 4 weights
// ---------------------------------------------------------------------------
__global__ void cvt_f32_f16(const float* __restrict__ in,
                            __half* __restrict__ out, int n)
{
    int i = (blockIdx.x * blockDim.x + threadIdx.x) * 8;
    if (i >= n) return;
    float4 a = *(const float4*)(in + i);
    float4 b = *(const float4*)(in + i + 4);
    uint4 o;
    o.x = packh2(a.x, a.y); o.y = packh2(a.z, a.w);
    o.z = packh2(b.x, b.y); o.w = packh2(b.z, b.w);
    *(uint4*)(out + i) = o;
}

__global__ void cvt_weights(const float* w0, const float* w1,
                            const float* w2, const float* w3,
                            __half* o0, __half* o1, __half* o2, __half* o3)
{
    const float* src[4] = {w0, w1, w2, w3};
    __half*      dst[4] = {o0, o1, o2, o3};
    const float* in  = src[blockIdx.y];
    __half*      out = dst[blockIdx.y];
    int i = (blockIdx.x * blockDim.x + threadIdx.x) * 8;
    float4 a = *(const float4*)(in + i);
    float4 b = *(const float4*)(in + i + 4);
    uint4 o;
    o.x = packh2(a.x, a.y); o.y = packh2(a.z, a.w);
    o.z = packh2(b.x, b.y); o.w = packh2(b.z, b.w);
    *(uint4*)(out + i) = o;
}

// ---------------------------------------------------------------------------
// Pure FP16 GEMM, 3-stage cp.async pipeline, ONE barrier per k-tile.
// (unchanged from R12)
// ---------------------------------------------------------------------------
#define GSTR   40
#define GTILEB (128 * GSTR * 2)
#define GEMM_SMEM_BYTES (6 * GTILEB)

template<typename OutT>
__global__ __launch_bounds__(256, 2)
void hgemm_f16(const __half* __restrict__ A, const __half* __restrict__ B,
               const float* __restrict__ bias, OutT* __restrict__ C)
{
    extern __shared__ char smc[];
    const uint32_t sb = smem_to_u32(smc);
    const int tid  = threadIdx.x;
    const int wid  = tid >> 5;
    const int lane = tid & 31;
    const int g    = lane >> 2;
    const int tg   = lane & 3;
    const int warp_m = wid & 1;
    const int warp_n = wid >> 1;
    const int m0 = blockIdx.y * 128;
    const int n0 = blockIdx.x * 128;

    const int lr = tid >> 1;
    const int lc = (tid & 1) * 16;
    const __half* Ag = A + (size_t)(m0 + lr) * GK + lc;
    const __half* Bg = B + (size_t)(n0 + lr) * GK + lc;
    const uint32_t sdst = (uint32_t)(lr * (GSTR * 2) + lc * 2);

    const uint32_t aoff = (uint32_t)(((lane & 15) * GSTR + (lane >> 4) * 8) * 2);
    const uint32_t boff = (uint32_t)(((lane & 7) * GSTR + ((lane >> 3) & 1) * 8) * 2);

    #pragma unroll
    for (int p = 0; p < 2; ++p) {
        cpa16(sb + p * GTILEB + sdst,            Ag + p * 32);
        cpa16(sb + p * GTILEB + sdst + 16,       Ag + p * 32 + 8);
        cpa16(sb + (3 + p) * GTILEB + sdst,      Bg + p * 32);
        cpa16(sb + (3 + p) * GTILEB + sdst + 16, Bg + p * 32 + 8);
        CP_COMMIT();
    }

    float acc[4][4][4];
    #pragma unroll
    for (int mt = 0; mt < 4; ++mt)
        #pragma unroll
        for (int nt = 0; nt < 4; ++nt)
            #pragma unroll
            for (int u = 0; u < 4; ++u) acc[mt][nt][u] = 0.0f;

    const int NT = GK / 32;
    int slot = 0, wslot = 2;
    for (int kt = 0; kt < NT; ++kt) {
        if (kt + 1 < NT) {
            asm volatile("cp.async.wait_group 1;" ::: "memory");
        } else {
            asm volatile("cp.async.wait_group 0;" ::: "memory");
        }
        __syncthreads();

        if (kt + 2 < NT) {
            const __half* Ag2 = Ag + (kt + 2) * 32;
            const __half* Bg2 = Bg + (kt + 2) * 32;
            cpa16(sb + wslot * GTILEB + sdst,            Ag2);
            cpa16(sb + wslot * GTILEB + sdst + 16,       Ag2 + 8);
            cpa16(sb + (3 + wslot) * GTILEB + sdst,      Bg2);
            cpa16(sb + (3 + wslot) * GTILEB + sdst + 16, Bg2 + 8);
            CP_COMMIT();
            if (++wslot == 3) wslot = 0;
        }

        const uint32_t AB = sb + slot * GTILEB;
        const uint32_t BB = sb + (3 + slot) * GTILEB;
        if (++slot == 3) slot = 0;

        #pragma unroll
        for (int ks = 0; ks < 2; ++ks) {
            uint32_t af[4][4], bf[4][2];
            #pragma unroll
            for (int mt = 0; mt < 4; ++mt)
                ldsm_x4(AB + (uint32_t)((warp_m * 64 + mt * 16) * GSTR * 2 + ks * 32)
                           + aoff, af[mt]);
            #pragma unroll
            for (int nt = 0; nt < 4; ++nt)
                ldsm_x2(BB + (uint32_t)((warp_n * 32 + nt * 8) * GSTR * 2 + ks * 32)
                           + boff, bf[nt][0], bf[nt][1]);
            #pragma unroll
            for (int mt = 0; mt < 4; ++mt)
                #pragma unroll
                for (int nt = 0; nt < 4; ++nt)
                    mma_f16(acc[mt][nt], af[mt], bf[nt][0], bf[nt][1]);
        }
    }

    #pragma unroll
    for (int nt = 0; nt < 4; ++nt) {
        const int col = n0 + warp_n * 32 + nt * 8 + tg * 2;
        const float b0 = bias[col], b1 = bias[col + 1];
        #pragma unroll
        for (int mt = 0; mt < 4; ++mt) {
            const int row = m0 + warp_m * 64 + mt * 16 + g;
            if (sizeof(OutT) == 2) {
                __half* Ch = (__half*)C;
                *(uint32_t*)(Ch + (size_t)row * D_M + col) =
                    packh2(acc[mt][nt][0] + b0, acc[mt][nt][1] + b1);
                *(uint32_t*)(Ch + (size_t)(row + 8) * D_M + col) =
                    packh2(acc[mt][nt][2] + b0, acc[mt][nt][3] + b1);
            } else {
                float* Cf = (float*)C;
                *(float2*)(Cf + (size_t)row * D_M + col) =
                    make_float2(acc[mt][nt][0] + b0, acc[mt][nt][1] + b1);
                *(float2*)(Cf + (size_t)(row + 8) * D_M + col) =
                    make_float2(acc[mt][nt][2] + b0, acc[mt][nt][3] + b1);
            }
        }
    }
}

// ---------------------------------------------------------------------------
// Flash attention — R13: 32 q-rows per warp (two m16 row-blocks), 256-row
// q-tile per CTA. Each K/V fragment is loaded ONCE and used by TWO MMAs
// (one per row-block) => K/V LDS per unit work HALVED. Register-P (R12).
// launch_bounds(256,1): ~190-reg peak, 8 warps/SM.
// ---------------------------------------------------------------------------
#define SK    64
#define KSTRH 72                      // halves per K/V smem row (144 B)
#define KVTB  (SK * KSTRH * 2)        // 9216 B per tile
#define OFF_VH (2 * KVTB)
#define FA_SMEM_BYTES (4 * KVTB)      // 36864 B

// softmax for one row-block: scale+mask, rowmax, exp, pack pf, update m/l/oacc
__device__ __forceinline__ void softmax_block(
    float sacc[8][4], float rA, float rB,
    float& mA, float& lA, float& mB, float& lB,
    float oacc[8][4], uint32_t pf[8][2])
{
    float mxA = -1e30f, mxB = -1e30f;
    #pragma unroll
    for (int nt = 0; nt < 8; ++nt) {
        sacc[nt][0] *= rA; sacc[nt][1] *= rA;
        sacc[nt][2] *= rB; sacc[nt][3] *= rB;
        mxA = fmaxf(mxA, fmaxf(sacc[nt][0], sacc[nt][1]));
        mxB = fmaxf(mxB, fmaxf(sacc[nt][2], sacc[nt][3]));
    }
    mxA = fmaxf(mxA, __shfl_xor_sync(0xffffffffu, mxA, 1));
    mxA = fmaxf(mxA, __shfl_xor_sync(0xffffffffu, mxA, 2));
    mxB = fmaxf(mxB, __shfl_xor_sync(0xffffffffu, mxB, 1));
    mxB = fmaxf(mxB, __shfl_xor_sync(0xffffffffu, mxB, 2));

    const float mnA = fmaxf(mA, mxA), mnB = fmaxf(mB, mxB);
    const float cfA = __expf(mA - mnA), cfB = __expf(mB - mnB);
    float rsA = 0.0f, rsB = 0.0f;
    #pragma unroll
    for (int nt = 0; nt < 8; ++nt) {
        float p0 = __expf(sacc[nt][0] - mnA);
        float p1 = __expf(sacc[nt][1] - mnA);
        float p2 = __expf(sacc[nt][2] - mnB);
        float p3 = __expf(sacc[nt][3] - mnB);
        rsA += p0 + p1;
        rsB += p2 + p3;
        pf[nt][0] = packh2(p0, p1);
        pf[nt][1] = packh2(p2, p3);
    }
    rsA += __shfl_xor_sync(0xffffffffu, rsA, 1);
    rsA += __shfl_xor_sync(0xffffffffu, rsA, 2);
    rsB += __shfl_xor_sync(0xffffffffu, rsB, 1);
    rsB += __shfl_xor_sync(0xffffffffu, rsB, 2);

    mA = mnA; lA = lA * cfA + rsA;
    mB = mnB; lB = lB * cfB + rsB;
    #pragma unroll
    for (int nt = 0; nt < 8; ++nt) {
        oacc[nt][0] *= cfA; oacc[nt][1] *= cfA;
        oacc[nt][2] *= cfB; oacc[nt][3] *= cfB;
    }
}

__global__ __launch_bounds__(256, 1)
void flash_attn_f16(const __half* __restrict__ Q, const __half* __restrict__ K,
                    const __half* __restrict__ V, const int* __restrict__ mask,
                    __half* __restrict__ ctx)
{
    extern __shared__ char smc[];
    const uint32_t sb = smem_to_u32(smc);

    const int tid  = threadIdx.x;
    const int wid  = tid >> 5;
    const int lane = tid & 31;
    const int g    = lane >> 2;
    const int tg   = lane & 3;
    const int t0 = blockIdx.x * 256;        // 256-row q-tile
    const int h  = blockIdx.y;
    const int n  = blockIdx.z;

    // two row-blocks per warp: rows wb+g/wb+g+8 and wb+16+g/wb+16+g+8
    const int wb = wid * 32;
    const size_t qr0 = (size_t)(n * T_S + t0 + wb + g);
    const size_t qr1 = qr0 + 16;
    const __half* Q00 = Q + qr0 * D_M + h * DH;
    const __half* Q01 = Q00 + (size_t)8 * D_M;
    const __half* Q10 = Q + qr1 * D_M + h * DH;
    const __half* Q11 = Q10 + (size_t)8 * D_M;
    uint32_t qf0[4][4], qf1[4][4];
    #pragma unroll
    for (int ks = 0; ks < 4; ++ks) {
        const int c = ks * 16 + 2 * tg;
        qf0[ks][0] = *(const uint32_t*)(Q00 + c);
        qf0[ks][1] = *(const uint32_t*)(Q01 + c);
        qf0[ks][2] = *(const uint32_t*)(Q00 + c + 8);
        qf0[ks][3] = *(const uint32_t*)(Q01 + c + 8);
        qf1[ks][0] = *(const uint32_t*)(Q10 + c);
        qf1[ks][1] = *(const uint32_t*)(Q11 + c);
        qf1[ks][2] = *(const uint32_t*)(Q10 + c + 8);
        qf1[ks][3] = *(const uint32_t*)(Q11 + c + 8);
    }

    const int mbase = n * T_S + t0 + wb;
    const float r00 = (mask[mbase + g]      != 0) ? 0.125f : 0.0f;
    const float r01 = (mask[mbase + g + 8]  != 0) ? 0.125f : 0.0f;
    const float r10 = (mask[mbase + g + 16] != 0) ? 0.125f : 0.0f;
    const float r11 = (mask[mbase + g + 24] != 0) ? 0.125f : 0.0f;

    float m00 = -1e30f, l00 = 0.0f, m01 = -1e30f, l01 = 0.0f;
    float m10 = -1e30f, l10 = 0.0f, m11 = -1e30f, l11 = 0.0f;
    float oacc0[8][4], oacc1[8][4];
    #pragma unroll
    for (int nt = 0; nt < 8; ++nt)
        #pragma unroll
        for (int u = 0; u < 4; ++u) { oacc0[nt][u] = 0.0f; oacc1[nt][u] = 0.0f; }

    const int cr = tid >> 2;
    const int cq = (tid & 3) * 16;
    const __half* Kg = K + ((size_t)(n * T_S) + cr) * D_M + h * DH + cq;
    const __half* Vg = V + ((size_t)(n * T_S) + cr) * D_M + h * DH + cq;
    const uint32_t cdst = (uint32_t)(cr * (KSTRH * 2) + cq * 2);

    const uint32_t koff = (uint32_t)(((lane & 7) * KSTRH + ((lane >> 3) & 1) * 8) * 2);
    const uint32_t voff = (uint32_t)((lane & 15) * KSTRH * 2);

    cpa16(sb + cdst,               Kg);
    cpa16(sb + cdst + 16,          Kg + 8);
    cpa16(sb + OFF_VH + cdst,      Vg);
    cpa16(sb + OFF_VH + cdst + 16, Vg + 8);
    CP_COMMIT();

    const int NST = T_S / SK;   // 32
    for (int st = 0; st < NST; ++st) {
        const int buf = st & 1;
        asm volatile("cp.async.wait_group 0;" ::: "memory");
        __syncthreads();

        if (st + 1 < NST) {
            const int nb = buf ^ 1;
            const size_t go = (size_t)(st + 1) * SK * D_M;
            cpa16(sb + nb * KVTB + cdst,               Kg + go);
            cpa16(sb + nb * KVTB + cdst + 16,          Kg + go + 8);
            cpa16(sb + OFF_VH + nb * KVTB + cdst,      Vg + go);
            cpa16(sb + OFF_VH + nb * KVTB + cdst + 16, Vg + go + 8);
            CP_COMMIT();
        }

        const uint32_t KhB = sb + buf * KVTB;
        const uint32_t VhB = sb + OFF_VH + buf * KVTB;

        // ---- S = Q K^T : each K fragment feeds BOTH row-blocks ----
        float sacc0[8][4], sacc1[8][4];
        #pragma unroll
        for (int nt = 0; nt < 8; ++nt)
            #pragma unroll
            for (int u = 0; u < 4; ++u) { sacc0[nt][u] = 0.0f; sacc1[nt][u] = 0.0f; }

        #pragma unroll
        for (int ks = 0; ks < 4; ++ks) {
            #pragma unroll
            for (int nt = 0; nt < 8; ++nt) {
                uint32_t b0, b1;
                ldsm_x2(KhB + (uint32_t)((nt * 8 * KSTRH + ks * 16) * 2) + koff, b0, b1);
                mma_f16(sacc0[nt], qf0[ks], b0, b1);
                mma_f16(sacc1[nt], qf1[ks], b0, b1);
            }
        }

        // ---- softmax per row-block -> register P ----
        uint32_t pf0[8][2], pf1[8][2];
        softmax_block(sacc0, r00, r01, m00, l00, m01, l01, oacc0, pf0);
        softmax_block(sacc1, r10, r11, m10, l10, m11, l11, oacc1, pf1);

        // ---- O += P V : each V fragment feeds BOTH row-blocks ----
        #pragma unroll
        for (int ks = 0; ks < 4; ++ks) {
            uint32_t a0[4], a1[4];
            a0[0] = pf0[2 * ks][0];     a0[1] = pf0[2 * ks][1];
            a0[2] = pf0[2 * ks + 1][0]; a0[3] = pf0[2 * ks + 1][1];
            a1[0] = pf1[2 * ks][0];     a1[1] = pf1[2 * ks][1];
            a1[2] = pf1[2 * ks + 1][0]; a1[3] = pf1[2 * ks + 1][1];
            #pragma unroll
            for (int nt = 0; nt < 8; ++nt) {
                uint32_t b0, b1;
                ldsm_x2t(VhB + (uint32_t)((ks * 16 * KSTRH + nt * 8) * 2) + voff, b0, b1);
                mma_f16(oacc0[nt], a0, b0, b1);
                mma_f16(oacc1[nt], a1, b0, b1);
            }
        }
    }

    // ---- epilogue: two row-blocks ----
    const float i00 = 1.0f / l00, i01 = 1.0f / l01;
    const float i10 = 1.0f / l10, i11 = 1.0f / l11;
    __half* o00 = ctx + qr0 * D_M + h * DH;
    __half* o01 = o00 + (size_t)8 * D_M;
    __half* o10 = ctx + qr1 * D_M + h * DH;
    __half* o11 = o10 + (size_t)8 * D_M;
    #pragma unroll
    for (int nt = 0; nt < 8; ++nt) {
        const int col = nt * 8 + tg * 2;
        *(uint32_t*)(o00 + col) = packh2(oacc0[nt][0] * i00, oacc0[nt][1] * i00);
        *(uint32_t*)(o01 + col) = packh2(oacc0[nt][2] * i01, oacc0[nt][3] * i01);
        *(uint32_t*)(o10 + col) = packh2(oacc1[nt][0] * i10, oacc1[nt][1] * i10);
        *(uint32_t*)(o11 + col) = packh2(oacc1[nt][2] * i11, oacc1[nt][3] * i11);
    }
}

// ---------------------------------------------------------------------------
// Launch
// ---------------------------------------------------------------------------
extern "C" void kernel_launch(void* const* d_in, const int* in_sizes, int n_in,
                              void* d_out, int out_size)
{
    (void)in_sizes; (void)n_in; (void)out_size;

    const float* query = (const float*)d_in[0];
    const int*   mask  = (const int*)  d_in[1];
    const float* Wq    = (const float*)d_in[2];
    const float* bq    = (const float*)d_in[3];
    const float* Wk    = (const float*)d_in[4];
    const float* bk    = (const float*)d_in[5];
    const float* Wv    = (const float*)d_in[6];
    const float* bv    = (const float*)d_in[7];
    const float* Wo    = (const float*)d_in[8];
    const float* bo    = (const float*)d_in[9];
    float* out = (float*)d_out;

    __half *qh, *Qh, *Kh, *Vh, *ctxh, *Wqh, *Wkh, *Wvh, *Woh;
    cudaGetSymbolAddress((void**)&qh,   g_qh);
    cudaGetSymbolAddress((void**)&Qh,   g_Qh);
    cudaGetSymbolAddress((void**)&Kh,   g_Kh);
    cudaGetSymbolAddress((void**)&Vh,   g_Vh);
    cudaGetSymbolAddress((void**)&ctxh, g_ctxh);
    cudaGetSymbolAddress((void**)&Wqh,  g_Wqh);
    cudaGetSymbolAddress((void**)&Wkh,  g_Wkh);
    cudaGetSymbolAddress((void**)&Wvh,  g_Wvh);
    cudaGetSymbolAddress((void**)&Woh,  g_Woh);

    cudaFuncSetAttribute(hgemm_f16<__half>,
                         cudaFuncAttributeMaxDynamicSharedMemorySize,
                         GEMM_SMEM_BYTES);
    cudaFuncSetAttribute(hgemm_f16<float>,
                         cudaFuncAttributeMaxDynamicSharedMemorySize,
                         GEMM_SMEM_BYTES);
    cudaFuncSetAttribute(flash_attn_f16,
                         cudaFuncAttributeMaxDynamicSharedMemorySize,
                         FA_SMEM_BYTES);

    const int nQ = MROWS * D_M;
    const int nW = D_M * D_M;
    cvt_f32_f16<<<nQ / 8 / 256, 256>>>(query, qh, nQ);
    cvt_weights<<<dim3(nW / 8 / 256, 4), 256>>>(Wq, Wk, Wv, Wo,
                                                Wqh, Wkh, Wvh, Woh);

    dim3 gemm_grid(D_M / 128, MROWS / 128);  // (8, 64)

    hgemm_f16<__half><<<gemm_grid, 256, GEMM_SMEM_BYTES>>>(qh, Wqh, bq, Qh);
    hgemm_f16<__half><<<gemm_grid, 256, GEMM_SMEM_BYTES>>>(qh, Wkh, bk, Kh);
    hgemm_f16<__half><<<gemm_grid, 256, GEMM_SMEM_BYTES>>>(qh, Wvh, bv, Vh);

    flash_attn_f16<<<dim3(T_S / 256, H_N, N_B), 256, FA_SMEM_BYTES>>>(
        Qh, Kh, Vh, mask, ctxh);

    hgemm_f16<float><<<gemm_grid, 256, GEMM_SMEM_BYTES>>>(ctxh, Woh, bo, out);
}

// round 14
// speedup vs baseline: 1.0404x; 1.0404x over previous
#include <cuda_runtime.h>
#include <cuda_fp16.h>
#include <math.h>
#include <stdint.h>

// Problem constants
#define N_B   4
#define T_S   2048
#define D_M   1024
#define H_N   16
#define DH    64
#define MROWS (N_B * T_S)   // 8192
#define GK    1024          // GEMM K

// ---------------------------------------------------------------------------
// Scratch (alloc-free rule: __device__ globals) — all f16
// ---------------------------------------------------------------------------
__device__ __half g_qh  [(size_t)MROWS * D_M];
__device__ __half g_Qh  [(size_t)MROWS * D_M];
__device__ __half g_Kh  [(size_t)MROWS * D_M];
__device__ __half g_Vh  [(size_t)MROWS * D_M];
__device__ __half g_ctxh[(size_t)MROWS * D_M];
__device__ __half g_Wqh [(size_t)D_M * D_M];
__device__ __half g_Wkh [(size_t)D_M * D_M];
__device__ __half g_Wvh [(size_t)D_M * D_M];
__device__ __half g_Woh [(size_t)D_M * D_M];

// ---------------------------------------------------------------------------
// Helpers (sm_100 plain target: NO tcgen05)
// ---------------------------------------------------------------------------
__device__ __forceinline__ uint32_t smem_to_u32(const void* p) {
    uint32_t a;
    asm("{ .reg .u64 t; cvta.to.shared.u64 t, %1; cvt.u32.u64 %0, t; }"
        : "=r"(a) : "l"(p));
    return a;
}
__device__ __forceinline__ void cpa16(uint32_t dst, const void* src) {
    asm volatile("cp.async.cg.shared.global [%0], [%1], 16;"
                 :: "r"(dst), "l"(src) : "memory");
}
#define CP_COMMIT() asm volatile("cp.async.commit_group;" ::: "memory")

__device__ __forceinline__ uint32_t packh2(float lo, float hi) {
    __half2 h = __floats2half2_rn(lo, hi);
    return *(uint32_t*)&h;
}
// D(16x8,f32) += A(16x16,f16 row) * B(16x8,f16 col)
__device__ __forceinline__ void mma_f16(float* d, const uint32_t* a,
                                        uint32_t b0, uint32_t b1) {
    asm volatile(
        "mma.sync.aligned.m16n8k16.row.col.f32.f16.f16.f32 "
        "{%0,%1,%2,%3}, {%4,%5,%6,%7}, {%8,%9}, {%0,%1,%2,%3};"
        : "+f"(d[0]), "+f"(d[1]), "+f"(d[2]), "+f"(d[3])
        : "r"(a[0]), "r"(a[1]), "r"(a[2]), "r"(a[3]),
          "r"(b0), "r"(b1));
}
__device__ __forceinline__ void ldsm_x2(uint32_t addr, uint32_t& r0, uint32_t& r1) {
    asm volatile("ldmatrix.sync.aligned.m8n8.x2.shared.b16 {%0,%1}, [%2];"
                 : "=r"(r0), "=r"(r1) : "r"(addr));
}
__device__ __forceinline__ void ldsm_x2t(uint32_t addr, uint32_t& r0, uint32_t& r1) {
    asm volatile("ldmatrix.sync.aligned.m8n8.x2.trans.shared.b16 {%0,%1}, [%2];"
                 : "=r"(r0), "=r"(r1) : "r"(addr));
}
__device__ __forceinline__ void ldsm_x4(uint32_t addr, uint32_t* r) {
    asm volatile("ldmatrix.sync.aligned.m8n8.x4.shared.b16 {%0,%1,%2,%3}, [%4];"
                 : "=r"(r[0]), "=r"(r[1]), "=r"(r[2]), "=r"(r[3]) : "r"(addr));
}

// ---------------------------------------------------------------------------
// fp32 -> fp16 converts
// ---------------------------------------------------------------------------
__global__ void cvt_f32_f16(const float* __restrict__ in,
                            __half* __restrict__ out, int n)
{
    int i = (blockIdx.x * blockDim.x + threadIdx.x) * 8;
    if (i >= n) return;
    float4 a = *(const float4*)(in + i);
    float4 b = *(const float4*)(in + i + 4);
    uint4 o;
    o.x = packh2(a.x, a.y); o.y = packh2(a.z, a.w);
    o.z = packh2(b.x, b.y); o.w = packh2(b.z, b.w);
    *(uint4*)(out + i) = o;
}

__global__ void cvt_weights(const float* w0, const float* w1,
                            const float* w2, const float* w3,
                            __half* o0, __half* o1, __half* o2, __half* o3)
{
    const float* src[4] = {w0, w1, w2, w3};
    __half*      dst[4] = {o0, o1, o2, o3};
    const float* in  = src[blockIdx.y];
    __half*      out = dst[blockIdx.y];
    int i = (blockIdx.x * blockDim.x + threadIdx.x) * 8;
    float4 a = *(const float4*)(in + i);
    float4 b = *(const float4*)(in + i + 4);
    uint4 o;
    o.x = packh2(a.x, a.y); o.y = packh2(a.z, a.w);
    o.z = packh2(b.x, b.y); o.w = packh2(b.z, b.w);
    *(uint4*)(out + i) = o;
}

// ---------------------------------------------------------------------------
// FP16 GEMM core, BK=64: 64 MMAs/warp per barrier (16 barriers total, was 32).
// 2-stage cp.async, ONE barrier per k-tile (slot overwritten at iter kt was
// last read at kt-1, sealed by the intervening barrier).
// 128x128 CTA tile, 8 warps (2M x 4N). GSTR=72 (flash-validated stride).
// ---------------------------------------------------------------------------
#define GSTR   72                       // halves per smem row (144 B)
#define GTILEB (128 * GSTR * 2)         // 18432 B per operand-tile
#define GEMM_SMEM_BYTES (4 * GTILEB)    // A0 A1 B0 B1 = 73728 B

template<typename OutT>
__device__ __forceinline__ void hgemm_core(
    const __half* __restrict__ A, const __half* __restrict__ B,
    const float* __restrict__ bias, OutT* __restrict__ C,
    char* smc, int m0, int n0)
{
    const uint32_t sb = smem_to_u32(smc);
    const int tid  = threadIdx.x;
    const int wid  = tid >> 5;
    const int lane = tid & 31;
    const int g    = lane >> 2;
    const int tg   = lane & 3;
    const int warp_m = wid & 1;
    const int warp_n = wid >> 1;

    // loader: row = tid>>1, 64-byte half-row = tid&1 (4 cp.async chunks each)
    const int lr = tid >> 1;
    const int lc = (tid & 1) * 32;          // halves
    const __half* Ag = A + (size_t)(m0 + lr) * GK + lc;
    const __half* Bg = B + (size_t)(n0 + lr) * GK + lc;
    const uint32_t sdst = (uint32_t)(lr * (GSTR * 2) + lc * 2);   // bytes

    const uint32_t aoff = (uint32_t)(((lane & 15) * GSTR + (lane >> 4) * 8) * 2);
    const uint32_t boff = (uint32_t)(((lane & 7) * GSTR + ((lane >> 3) & 1) * 8) * 2);

    // prologue: k-tile 0 -> slot 0
    #pragma unroll
    for (int j = 0; j < 4; ++j) {
        cpa16(sb + sdst + j * 16,              Ag + j * 8);
        cpa16(sb + 2 * GTILEB + sdst + j * 16, Bg + j * 8);
    }
    CP_COMMIT();

    float acc[4][4][4];
    #pragma unroll
    for (int mt = 0; mt < 4; ++mt)
        #pragma unroll
        for (int nt = 0; nt < 4; ++nt)
            #pragma unroll
            for (int u = 0; u < 4; ++u) acc[mt][nt][u] = 0.0f;

    const int NT = GK / 64;   // 16 k-tiles
    for (int kt = 0; kt < NT; ++kt) {
        const int buf = kt & 1;
        asm volatile("cp.async.wait_group 0;" ::: "memory");
        __syncthreads();

        if (kt + 1 < NT) {
            const int nb = buf ^ 1;
            const __half* Ag2 = Ag + (kt + 1) * 64;
            const __half* Bg2 = Bg + (kt + 1) * 64;
            #pragma unroll
            for (int j = 0; j < 4; ++j) {
                cpa16(sb + nb * GTILEB + sdst + j * 16,       Ag2 + j * 8);
                cpa16(sb + (2 + nb) * GTILEB + sdst + j * 16, Bg2 + j * 8);
            }
            CP_COMMIT();
        }

        const uint32_t AB = sb + buf * GTILEB;
        const uint32_t BB = sb + (2 + buf) * GTILEB;

        #pragma unroll
        for (int ks = 0; ks < 4; ++ks) {        // 4 k16 steps (BK=64)
            uint32_t af[4][4], bf[4][2];
            #pragma unroll
            for (int mt = 0; mt < 4; ++mt)
                ldsm_x4(AB + (uint32_t)((warp_m * 64 + mt * 16) * GSTR * 2 + ks * 32)
                           + aoff, af[mt]);
            #pragma unroll
            for (int nt = 0; nt < 4; ++nt)
                ldsm_x2(BB + (uint32_t)((warp_n * 32 + nt * 8) * GSTR * 2 + ks * 32)
                           + boff, bf[nt][0], bf[nt][1]);
            #pragma unroll
            for (int mt = 0; mt < 4; ++mt)
                #pragma unroll
                for (int nt = 0; nt < 4; ++nt)
                    mma_f16(acc[mt][nt], af[mt], bf[nt][0], bf[nt][1]);
        }
    }

    #pragma unroll
    for (int nt = 0; nt < 4; ++nt) {
        const int col = n0 + warp_n * 32 + nt * 8 + tg * 2;
        const float b0 = bias[col], b1 = bias[col + 1];
        #pragma unroll
        for (int mt = 0; mt < 4; ++mt) {
            const int row = m0 + warp_m * 64 + mt * 16 + g;
            if (sizeof(OutT) == 2) {
                __half* Ch = (__half*)C;
                *(uint32_t*)(Ch + (size_t)row * D_M + col) =
                    packh2(acc[mt][nt][0] + b0, acc[mt][nt][1] + b1);
                *(uint32_t*)(Ch + (size_t)(row + 8) * D_M + col) =
                    packh2(acc[mt][nt][2] + b0, acc[mt][nt][3] + b1);
            } else {
                float* Cf = (float*)C;
                *(float2*)(Cf + (size_t)row * D_M + col) =
                    make_float2(acc[mt][nt][0] + b0, acc[mt][nt][1] + b1);
                *(float2*)(Cf + (size_t)(row + 8) * D_M + col) =
                    make_float2(acc[mt][nt][2] + b0, acc[mt][nt][3] + b1);
            }
        }
    }
}

// Fused QKV: blockIdx.z selects (W, bias, output). One launch, 1536 CTAs.
__global__ __launch_bounds__(256, 2)
void hgemm_qkv(const __half* __restrict__ A,
               const __half* B0, const __half* B1, const __half* B2,
               const float* bias0, const float* bias1, const float* bias2,
               __half* C0, __half* C1, __half* C2)
{
    extern __shared__ char smc[];
    const __half* Bsel[3]    = {B0, B1, B2};
    const float*  biassel[3] = {bias0, bias1, bias2};
    __half*       Csel[3]    = {C0, C1, C2};
    const int z = blockIdx.z;
    hgemm_core<__half>(A, Bsel[z], biassel[z], Csel[z], smc,
                       blockIdx.y * 128, blockIdx.x * 128);
}

__global__ __launch_bounds__(256, 2)
void hgemm_out(const __half* __restrict__ A, const __half* __restrict__ B,
               const float* __restrict__ bias, float* __restrict__ C)
{
    extern __shared__ char smc[];
    hgemm_core<float>(A, B, bias, C, smc, blockIdx.y * 128, blockIdx.x * 128);
}

// ---------------------------------------------------------------------------
// Flash attention — REVERTED to R12 (best measured): 128-row q-tile, 16 rows
// per warp, register-P, launch_bounds(256,2).
// ---------------------------------------------------------------------------
#define SK    64
#define KSTRH 72                      // halves per K/V smem row (144 B)
#define KVTB  (SK * KSTRH * 2)        // 9216 B per tile
#define OFF_VH (2 * KVTB)
#define FA_SMEM_BYTES (4 * KVTB)      // 36864 B

__global__ __launch_bounds__(256, 2)
void flash_attn_f16(const __half* __restrict__ Q, const __half* __restrict__ K,
                    const __half* __restrict__ V, const int* __restrict__ mask,
                    __half* __restrict__ ctx)
{
    extern __shared__ char smc[];
    const uint32_t sb = smem_to_u32(smc);

    const int tid  = threadIdx.x;
    const int wid  = tid >> 5;
    const int lane = tid & 31;
    const int g    = lane >> 2;
    const int tg   = lane & 3;
    const int t0 = blockIdx.x * 128;
    const int h  = blockIdx.y;
    const int n  = blockIdx.z;

    const size_t qrow = (size_t)(n * T_S + t0 + wid * 16 + g);
    const __half* Qp0 = Q + qrow * D_M + h * DH;
    const __half* Qp1 = Qp0 + (size_t)8 * D_M;
    uint32_t qf[4][4];
    #pragma unroll
    for (int ks = 0; ks < 4; ++ks) {
        const int c = ks * 16 + 2 * tg;
        qf[ks][0] = *(const uint32_t*)(Qp0 + c);
        qf[ks][1] = *(const uint32_t*)(Qp1 + c);
        qf[ks][2] = *(const uint32_t*)(Qp0 + c + 8);
        qf[ks][3] = *(const uint32_t*)(Qp1 + c + 8);
    }

    const float rsc0 = (mask[n * T_S + t0 + wid * 16 + g]     != 0) ? 0.125f : 0.0f;
    const float rsc1 = (mask[n * T_S + t0 + wid * 16 + g + 8] != 0) ? 0.125f : 0.0f;

    float m0 = -1e30f, l0 = 0.0f, m1 = -1e30f, l1 = 0.0f;
    float oacc[8][4];
    #pragma unroll
    for (int nt = 0; nt < 8; ++nt)
        #pragma unroll
        for (int u = 0; u < 4; ++u) oacc[nt][u] = 0.0f;

    const int cr = tid >> 2;
    const int cq = (tid & 3) * 16;
    const __half* Kg = K + ((size_t)(n * T_S) + cr) * D_M + h * DH + cq;
    const __half* Vg = V + ((size_t)(n * T_S) + cr) * D_M + h * DH + cq;
    const uint32_t cdst = (uint32_t)(cr * (KSTRH * 2) + cq * 2);

    const uint32_t koff = (uint32_t)(((lane & 7) * KSTRH + ((lane >> 3) & 1) * 8) * 2);
    const uint32_t voff = (uint32_t)((lane & 15) * KSTRH * 2);

    cpa16(sb + cdst,               Kg);
    cpa16(sb + cdst + 16,          Kg + 8);
    cpa16(sb + OFF_VH + cdst,      Vg);
    cpa16(sb + OFF_VH + cdst + 16, Vg + 8);
    CP_COMMIT();

    const int NST = T_S / SK;   // 32
    for (int st = 0; st < NST; ++st) {
        const int buf = st & 1;
        asm volatile("cp.async.wait_group 0;" ::: "memory");
        __syncthreads();

        if (st + 1 < NST) {
            const int nb = buf ^ 1;
            const size_t go = (size_t)(st + 1) * SK * D_M;
            cpa16(sb + nb * KVTB + cdst,               Kg + go);
            cpa16(sb + nb * KVTB + cdst + 16,          Kg + go + 8);
            cpa16(sb + OFF_VH + nb * KVTB + cdst,      Vg + go);
            cpa16(sb + OFF_VH + nb * KVTB + cdst + 16, Vg + go + 8);
            CP_COMMIT();
        }

        const uint32_t KhB = sb + buf * KVTB;
        const uint32_t VhB = sb + OFF_VH + buf * KVTB;

        float sacc[8][4];
        #pragma unroll
        for (int nt = 0; nt < 8; ++nt)
            #pragma unroll
            for (int u = 0; u < 4; ++u) sacc[nt][u] = 0.0f;

        #pragma unroll
        for (int ks = 0; ks < 4; ++ks) {
            #pragma unroll
            for (int nt = 0; nt < 8; ++nt) {
                uint32_t b0, b1;
                ldsm_x2(KhB + (uint32_t)((nt * 8 * KSTRH + ks * 16) * 2) + koff, b0, b1);
                mma_f16(sacc[nt], qf[ks], b0, b1);
            }
        }

        uint32_t pf[8][2];
        {
            float mx0 = -1e30f, mx1 = -1e30f;
            #pragma unroll
            for (int nt = 0; nt < 8; ++nt) {
                sacc[nt][0] *= rsc0; sacc[nt][1] *= rsc0;
                sacc[nt][2] *= rsc1; sacc[nt][3] *= rsc1;
                mx0 = fmaxf(mx0, fmaxf(sacc[nt][0], sacc[nt][1]));
                mx1 = fmaxf(mx1, fmaxf(sacc[nt][2], sacc[nt][3]));
            }
            mx0 = fmaxf(mx0, __shfl_xor_sync(0xffffffffu, mx0, 1));
            mx0 = fmaxf(mx0, __shfl_xor_sync(0xffffffffu, mx0, 2));
            mx1 = fmaxf(mx1, __shfl_xor_sync(0xffffffffu, mx1, 1));
            mx1 = fmaxf(mx1, __shfl_xor_sync(0xffffffffu, mx1, 2));

            const float mn0 = fmaxf(m0, mx0), mn1 = fmaxf(m1, mx1);
            const float cf0 = __expf(m0 - mn0), cf1 = __expf(m1 - mn1);
            float rs0 = 0.0f, rs1 = 0.0f;

            #pragma unroll
            for (int nt = 0; nt < 8; ++nt) {
                float p0 = __expf(sacc[nt][0] - mn0);
                float p1 = __expf(sacc[nt][1] - mn0);
                float p2 = __expf(sacc[nt][2] - mn1);
                float p3 = __expf(sacc[nt][3] - mn1);
                rs0 += p0 + p1;
                rs1 += p2 + p3;
                pf[nt][0] = packh2(p0, p1);
                pf[nt][1] = packh2(p2, p3);
            }
            rs0 += __shfl_xor_sync(0xffffffffu, rs0, 1);
            rs0 += __shfl_xor_sync(0xffffffffu, rs0, 2);
            rs1 += __shfl_xor_sync(0xffffffffu, rs1, 1);
            rs1 += __shfl_xor_sync(0xffffffffu, rs1, 2);

            m0 = mn0; l0 = l0 * cf0 + rs0;
            m1 = mn1; l1 = l1 * cf1 + rs1;
            #pragma unroll
            for (int nt = 0; nt < 8; ++nt) {
                oacc[nt][0] *= cf0; oacc[nt][1] *= cf0;
                oacc[nt][2] *= cf1; oacc[nt][3] *= cf1;
            }
        }

        #pragma unroll
        for (int ks = 0; ks < 4; ++ks) {
            uint32_t af[4];
            af[0] = pf[2 * ks][0];
            af[1] = pf[2 * ks][1];
            af[2] = pf[2 * ks + 1][0];
            af[3] = pf[2 * ks + 1][1];
            #pragma unroll
            for (int nt = 0; nt < 8; ++nt) {
                uint32_t b0, b1;
                ldsm_x2t(VhB + (uint32_t)((ks * 16 * KSTRH + nt * 8) * 2) + voff, b0, b1);
                mma_f16(oacc[nt], af, b0, b1);
            }
        }
    }

    const float inv0 = 1.0f / l0, inv1 = 1.0f / l1;
    __half* op0 = ctx + qrow * D_M + h * DH;
    __half* op1 = op0 + (size_t)8 * D_M;
    #pragma unroll
    for (int nt = 0; nt < 8; ++nt) {
        const int col = nt * 8 + tg * 2;
        *(uint32_t*)(op0 + col) = packh2(oacc[nt][0] * inv0, oacc[nt][1] * inv0);
        *(uint32_t*)(op1 + col) = packh2(oacc[nt][2] * inv1, oacc[nt][3] * inv1);
    }
}

// ---------------------------------------------------------------------------
// Launch
// ---------------------------------------------------------------------------
extern "C" void kernel_launch(void* const* d_in, const int* in_sizes, int n_in,
                              void* d_out, int out_size)
{
    (void)in_sizes; (void)n_in; (void)out_size;

    const float* query = (const float*)d_in[0];
    const int*   mask  = (const int*)  d_in[1];
    const float* Wq    = (const float*)d_in[2];
    const float* bq    = (const float*)d_in[3];
    const float* Wk    = (const float*)d_in[4];
    const float* bk    = (const float*)d_in[5];
    const float* Wv    = (const float*)d_in[6];
    const float* bv    = (const float*)d_in[7];
    const float* Wo    = (const float*)d_in[8];
    const float* bo    = (const float*)d_in[9];
    float* out = (float*)d_out;

    __half *qh, *Qh, *Kh, *Vh, *ctxh, *Wqh, *Wkh, *Wvh, *Woh;
    cudaGetSymbolAddress((void**)&qh,   g_qh);
    cudaGetSymbolAddress((void**)&Qh,   g_Qh);
    cudaGetSymbolAddress((void**)&Kh,   g_Kh);
    cudaGetSymbolAddress((void**)&Vh,   g_Vh);
    cudaGetSymbolAddress((void**)&ctxh, g_ctxh);
    cudaGetSymbolAddress((void**)&Wqh,  g_Wqh);
    cudaGetSymbolAddress((void**)&Wkh,  g_Wkh);
    cudaGetSymbolAddress((void**)&Wvh,  g_Wvh);
    cudaGetSymbolAddress((void**)&Woh,  g_Woh);

    cudaFuncSetAttribute(hgemm_qkv,
                         cudaFuncAttributeMaxDynamicSharedMemorySize,
                         GEMM_SMEM_BYTES);
    cudaFuncSetAttribute(hgemm_out,
                         cudaFuncAttributeMaxDynamicSharedMemorySize,
                         GEMM_SMEM_BYTES);
    cudaFuncSetAttribute(flash_attn_f16,
                         cudaFuncAttributeMaxDynamicSharedMemorySize,
                         FA_SMEM_BYTES);

    const int nQ = MROWS * D_M;
    const int nW = D_M * D_M;
    cvt_f32_f16<<<nQ / 8 / 256, 256>>>(query, qh, nQ);
    cvt_weights<<<dim3(nW / 8 / 256, 4), 256>>>(Wq, Wk, Wv, Wo,
                                                Wqh, Wkh, Wvh, Woh);

    // Fused QKV: one launch, grid z selects weight/bias/output
    hgemm_qkv<<<dim3(D_M / 128, MROWS / 128, 3), 256, GEMM_SMEM_BYTES>>>(
        qh, Wqh, Wkh, Wvh, bq, bk, bv, Qh, Kh, Vh);

    flash_attn_f16<<<dim3(T_S / 128, H_N, N_B), 256, FA_SMEM_BYTES>>>(
        Qh, Kh, Vh, mask, ctxh);

    hgemm_out<<<dim3(D_M / 128, MROWS / 128), 256, GEMM_SMEM_BYTES>>>(
        ctxh, Woh, bo, out);
}

// round 15
// speedup vs baseline: 1.0474x; 1.0067x over previous
#include <cuda_runtime.h>
#include <cuda_fp16.h>
#include <math.h>
#include <stdint.h>

// Problem constants
#define N_B   4
#define T_S   2048
#define D_M   1024
#define H_N   16
#define DH    64
#define MROWS (N_B * T_S)   // 8192
#define GK    1024          // GEMM K

// ---------------------------------------------------------------------------
// Scratch (alloc-free rule: __device__ globals) — all f16
// ---------------------------------------------------------------------------
__device__ __half g_qh  [(size_t)MROWS * D_M];
__device__ __half g_Qh  [(size_t)MROWS * D_M];
__device__ __half g_Kh  [(size_t)MROWS * D_M];
__device__ __half g_Vh  [(size_t)MROWS * D_M];
__device__ __half g_ctxh[(size_t)MROWS * D_M];
__device__ __half g_Wqh [(size_t)D_M * D_M];
__device__ __half g_Wkh [(size_t)D_M * D_M];
__device__ __half g_Wvh [(size_t)D_M * D_M];
__device__ __half g_Woh [(size_t)D_M * D_M];

// ---------------------------------------------------------------------------
// Helpers (sm_100 plain target: NO tcgen05)
// ---------------------------------------------------------------------------
__device__ __forceinline__ uint32_t smem_to_u32(const void* p) {
    uint32_t a;
    asm("{ .reg .u64 t; cvta.to.shared.u64 t, %1; cvt.u32.u64 %0, t; }"
        : "=r"(a) : "l"(p));
    return a;
}
__device__ __forceinline__ void cpa16(uint32_t dst, const void* src) {
    asm volatile("cp.async.cg.shared.global [%0], [%1], 16;"
                 :: "r"(dst), "l"(src) : "memory");
}
#define CP_COMMIT() asm volatile("cp.async.commit_group;" ::: "memory")

__device__ __forceinline__ uint32_t packh2(float lo, float hi) {
    __half2 h = __floats2half2_rn(lo, hi);
    return *(uint32_t*)&h;
}
__device__ __forceinline__ float ex2f(float x) {   // single EX2 (same unit __expf uses)
    float y;
    asm("ex2.approx.f32 %0, %1;" : "=f"(y) : "f"(x));
    return y;
}
// D(16x8,f32) += A(16x16,f16 row) * B(16x8,f16 col)
__device__ __forceinline__ void mma_f16(float* d, const uint32_t* a,
                                        uint32_t b0, uint32_t b1) {
    asm volatile(
        "mma.sync.aligned.m16n8k16.row.col.f32.f16.f16.f32 "
        "{%0,%1,%2,%3}, {%4,%5,%6,%7}, {%8,%9}, {%0,%1,%2,%3};"
        : "+f"(d[0]), "+f"(d[1]), "+f"(d[2]), "+f"(d[3])
        : "r"(a[0]), "r"(a[1]), "r"(a[2]), "r"(a[3]),
          "r"(b0), "r"(b1));
}
__device__ __forceinline__ void ldsm_x4(uint32_t addr, uint32_t* r) {
    asm volatile("ldmatrix.sync.aligned.m8n8.x4.shared.b16 {%0,%1,%2,%3}, [%4];"
                 : "=r"(r[0]), "=r"(r[1]), "=r"(r[2]), "=r"(r[3]) : "r"(addr));
}
__device__ __forceinline__ void ldsm_x4t(uint32_t addr, uint32_t* r) {
    asm volatile("ldmatrix.sync.aligned.m8n8.x4.trans.shared.b16 {%0,%1,%2,%3}, [%4];"
                 : "=r"(r[0]), "=r"(r[1]), "=r"(r[2]), "=r"(r[3]) : "r"(addr));
}

// ---------------------------------------------------------------------------
// fp32 -> fp16 converts
// ---------------------------------------------------------------------------
__global__ void cvt_f32_f16(const float* __restrict__ in,
                            __half* __restrict__ out, int n)
{
    int i = (blockIdx.x * blockDim.x + threadIdx.x) * 8;
    if (i >= n) return;
    float4 a = *(const float4*)(in + i);
    float4 b = *(const float4*)(in + i + 4);
    uint4 o;
    o.x = packh2(a.x, a.y); o.y = packh2(a.z, a.w);
    o.z = packh2(b.x, b.y); o.w = packh2(b.z, b.w);
    *(uint4*)(out + i) = o;
}

__global__ void cvt_weights(const float* w0, const float* w1,
                            const float* w2, const float* w3,
                            __half* o0, __half* o1, __half* o2, __half* o3)
{
    const float* src[4] = {w0, w1, w2, w3};
    __half*      dst[4] = {o0, o1, o2, o3};
    const float* in  = src[blockIdx.y];
    __half*      out = dst[blockIdx.y];
    int i = (blockIdx.x * blockDim.x + threadIdx.x) * 8;
    float4 a = *(const float4*)(in + i);
    float4 b = *(const float4*)(in + i + 4);
    uint4 o;
    o.x = packh2(a.x, a.y); o.y = packh2(a.z, a.w);
    o.z = packh2(b.x, b.y); o.w = packh2(b.z, b.w);
    *(uint4*)(out + i) = o;
}

// ---------------------------------------------------------------------------
// FP16 GEMM core, BK=64, 2-stage cp.async, one barrier per k-tile.
// B-fragments now via ldsm_x4 (two 8-col blocks per instruction).
// ---------------------------------------------------------------------------
#define GSTR   72
#define GTILEB (128 * GSTR * 2)
#define GEMM_SMEM_BYTES (4 * GTILEB)

template<typename OutT>
__device__ __forceinline__ void hgemm_core(
    const __half* __restrict__ A, const __half* __restrict__ B,
    const float* __restrict__ bias, OutT* __restrict__ C,
    char* smc, int m0, int n0)
{
    const uint32_t sb = smem_to_u32(smc);
    const int tid  = threadIdx.x;
    const int wid  = tid >> 5;
    const int lane = tid & 31;
    const int g    = lane >> 2;
    const int tg   = lane & 3;
    const int warp_m = wid & 1;
    const int warp_n = wid >> 1;

    const int lr = tid >> 1;
    const int lc = (tid & 1) * 32;
    const __half* Ag = A + (size_t)(m0 + lr) * GK + lc;
    const __half* Bg = B + (size_t)(n0 + lr) * GK + lc;
    const uint32_t sdst = (uint32_t)(lr * (GSTR * 2) + lc * 2);

    const uint32_t aoff  = (uint32_t)(((lane & 15) * GSTR + (lane >> 4) * 8) * 2);
    // x4 B pattern: 8-lane groups -> (rows r0..7,k0)(r0..7,k1)(r8..15,k0)(r8..15,k1)
    const uint32_t boff4 = (uint32_t)((((lane & 7) + ((lane >> 4) << 3)) * GSTR) * 2
                                      + ((lane >> 3) & 1) * 16);

    #pragma unroll
    for (int j = 0; j < 4; ++j) {
        cpa16(sb + sdst + j * 16,              Ag + j * 8);
        cpa16(sb + 2 * GTILEB + sdst + j * 16, Bg + j * 8);
    }
    CP_COMMIT();

    float acc[4][4][4];
    #pragma unroll
    for (int mt = 0; mt < 4; ++mt)
        #pragma unroll
        for (int nt = 0; nt < 4; ++nt)
            #pragma unroll
            for (int u = 0; u < 4; ++u) acc[mt][nt][u] = 0.0f;

    const int NT = GK / 64;
    for (int kt = 0; kt < NT; ++kt) {
        const int buf = kt & 1;
        asm volatile("cp.async.wait_group 0;" ::: "memory");
        __syncthreads();

        if (kt + 1 < NT) {
            const int nb = buf ^ 1;
            const __half* Ag2 = Ag + (kt + 1) * 64;
            const __half* Bg2 = Bg + (kt + 1) * 64;
            #pragma unroll
            for (int j = 0; j < 4; ++j) {
                cpa16(sb + nb * GTILEB + sdst + j * 16,       Ag2 + j * 8);
                cpa16(sb + (2 + nb) * GTILEB + sdst + j * 16, Bg2 + j * 8);
            }
            CP_COMMIT();
        }

        const uint32_t AB = sb + buf * GTILEB;
        const uint32_t BB = sb + (2 + buf) * GTILEB;

        #pragma unroll
        for (int ks = 0; ks < 4; ++ks) {
            uint32_t af[4][4], bf[2][4];
            #pragma unroll
            for (int mt = 0; mt < 4; ++mt)
                ldsm_x4(AB + (uint32_t)((warp_m * 64 + mt * 16) * GSTR * 2 + ks * 32)
                           + aoff, af[mt]);
            #pragma unroll
            for (int ntp = 0; ntp < 2; ++ntp)
                ldsm_x4(BB + (uint32_t)((warp_n * 32 + ntp * 16) * GSTR * 2 + ks * 32)
                           + boff4, bf[ntp]);
            #pragma unroll
            for (int mt = 0; mt < 4; ++mt) {
                #pragma unroll
                for (int ntp = 0; ntp < 2; ++ntp) {
                    mma_f16(acc[mt][2 * ntp],     af[mt], bf[ntp][0], bf[ntp][1]);
                    mma_f16(acc[mt][2 * ntp + 1], af[mt], bf[ntp][2], bf[ntp][3]);
                }
            }
        }
    }

    #pragma unroll
    for (int nt = 0; nt < 4; ++nt) {
        const int col = n0 + warp_n * 32 + nt * 8 + tg * 2;
        const float b0 = bias[col], b1 = bias[col + 1];
        #pragma unroll
        for (int mt = 0; mt < 4; ++mt) {
            const int row = m0 + warp_m * 64 + mt * 16 + g;
            if (sizeof(OutT) == 2) {
                __half* Ch = (__half*)C;
                *(uint32_t*)(Ch + (size_t)row * D_M + col) =
                    packh2(acc[mt][nt][0] + b0, acc[mt][nt][1] + b1);
                *(uint32_t*)(Ch + (size_t)(row + 8) * D_M + col) =
                    packh2(acc[mt][nt][2] + b0, acc[mt][nt][3] + b1);
            } else {
                float* Cf = (float*)C;
                *(float2*)(Cf + (size_t)row * D_M + col) =
                    make_float2(acc[mt][nt][0] + b0, acc[mt][nt][1] + b1);
                *(float2*)(Cf + (size_t)(row + 8) * D_M + col) =
                    make_float2(acc[mt][nt][2] + b0, acc[mt][nt][3] + b1);
            }
        }
    }
}

__global__ __launch_bounds__(256, 2)
void hgemm_qkv(const __half* __restrict__ A,
               const __half* B0, const __half* B1, const __half* B2,
               const float* bias0, const float* bias1, const float* bias2,
               __half* C0, __half* C1, __half* C2)
{
    extern __shared__ char smc[];
    const __half* Bsel[3]    = {B0, B1, B2};
    const float*  biassel[3] = {bias0, bias1, bias2};
    __half*       Csel[3]    = {C0, C1, C2};
    const int z = blockIdx.z;
    hgemm_core<__half>(A, Bsel[z], biassel[z], Csel[z], smc,
                       blockIdx.y * 128, blockIdx.x * 128);
}

__global__ __launch_bounds__(256, 2)
void hgemm_out(const __half* __restrict__ A, const __half* __restrict__ B,
               const float* __restrict__ bias, float* __restrict__ C)
{
    extern __shared__ char smc[];
    hgemm_core<float>(A, B, bias, C, smc, blockIdx.y * 128, blockIdx.x * 128);
}

// ---------------------------------------------------------------------------
// Flash attention — R15: exp2-domain softmax (log2e folded into row scale,
// bare EX2 per element), conditional O-rescale (skip when max unchanged),
// K/V fragments via ldsm_x4 (half the LDS instruction count).
// ---------------------------------------------------------------------------
#define SK    64
#define KSTRH 72
#define KVTB  (SK * KSTRH * 2)
#define OFF_VH (2 * KVTB)
#define FA_SMEM_BYTES (4 * KVTB)      // 36864 B

#define LOG2E 1.4426950408889634f

__global__ __launch_bounds__(256, 2)
void flash_attn_f16(const __half* __restrict__ Q, const __half* __restrict__ K,
                    const __half* __restrict__ V, const int* __restrict__ mask,
                    __half* __restrict__ ctx)
{
    extern __shared__ char smc[];
    const uint32_t sb = smem_to_u32(smc);

    const int tid  = threadIdx.x;
    const int wid  = tid >> 5;
    const int lane = tid & 31;
    const int g    = lane >> 2;
    const int tg   = lane & 3;
    const int t0 = blockIdx.x * 128;
    const int h  = blockIdx.y;
    const int n  = blockIdx.z;

    const size_t qrow = (size_t)(n * T_S + t0 + wid * 16 + g);
    const __half* Qp0 = Q + qrow * D_M + h * DH;
    const __half* Qp1 = Qp0 + (size_t)8 * D_M;
    uint32_t qf[4][4];
    #pragma unroll
    for (int ks = 0; ks < 4; ++ks) {
        const int c = ks * 16 + 2 * tg;
        qf[ks][0] = *(const uint32_t*)(Qp0 + c);
        qf[ks][1] = *(const uint32_t*)(Qp1 + c);
        qf[ks][2] = *(const uint32_t*)(Qp0 + c + 8);
        qf[ks][3] = *(const uint32_t*)(Qp1 + c + 8);
    }

    // row scale folded with log2(e): softmax done in exp2 domain.
    const float rsc0 = (mask[n * T_S + t0 + wid * 16 + g]     != 0) ? 0.125f * LOG2E : 0.0f;
    const float rsc1 = (mask[n * T_S + t0 + wid * 16 + g + 8] != 0) ? 0.125f * LOG2E : 0.0f;

    float m0 = -1e30f, l0 = 0.0f, m1 = -1e30f, l1 = 0.0f;
    float oacc[8][4];
    #pragma unroll
    for (int nt = 0; nt < 8; ++nt)
        #pragma unroll
        for (int u = 0; u < 4; ++u) oacc[nt][u] = 0.0f;

    const int cr = tid >> 2;
    const int cq = (tid & 3) * 16;
    const __half* Kg = K + ((size_t)(n * T_S) + cr) * D_M + h * DH + cq;
    const __half* Vg = V + ((size_t)(n * T_S) + cr) * D_M + h * DH + cq;
    const uint32_t cdst = (uint32_t)(cr * (KSTRH * 2) + cq * 2);

    // x4 fragment offsets
    const uint32_t koff4 = (uint32_t)((((lane & 7) + ((lane >> 4) << 3)) * KSTRH) * 2
                                      + ((lane >> 3) & 1) * 16);
    const uint32_t voff4 = (uint32_t)((lane & 15) * KSTRH * 2 + ((lane >> 4) & 1) * 16);

    cpa16(sb + cdst,               Kg);
    cpa16(sb + cdst + 16,          Kg + 8);
    cpa16(sb + OFF_VH + cdst,      Vg);
    cpa16(sb + OFF_VH + cdst + 16, Vg + 8);
    CP_COMMIT();

    const int NST = T_S / SK;   // 32
    for (int st = 0; st < NST; ++st) {
        const int buf = st & 1;
        asm volatile("cp.async.wait_group 0;" ::: "memory");
        __syncthreads();

        if (st + 1 < NST) {
            const int nb = buf ^ 1;
            const size_t go = (size_t)(st + 1) * SK * D_M;
            cpa16(sb + nb * KVTB + cdst,               Kg + go);
            cpa16(sb + nb * KVTB + cdst + 16,          Kg + go + 8);
            cpa16(sb + OFF_VH + nb * KVTB + cdst,      Vg + go);
            cpa16(sb + OFF_VH + nb * KVTB + cdst + 16, Vg + go + 8);
            CP_COMMIT();
        }

        const uint32_t KhB = sb + buf * KVTB;
        const uint32_t VhB = sb + OFF_VH + buf * KVTB;

        // ---- S = Q K^T : ldsm_x4 serves two n-tiles at once ----
        float sacc[8][4];
        #pragma unroll
        for (int nt = 0; nt < 8; ++nt)
            #pragma unroll
            for (int u = 0; u < 4; ++u) sacc[nt][u] = 0.0f;

        #pragma unroll
        for (int ks = 0; ks < 4; ++ks) {
            #pragma unroll
            for (int nt = 0; nt < 8; nt += 2) {
                uint32_t r[4];
                ldsm_x4(KhB + (uint32_t)((nt * 8 * KSTRH + ks * 16) * 2) + koff4, r);
                mma_f16(sacc[nt],     qf[ks], r[0], r[1]);
                mma_f16(sacc[nt + 1], qf[ks], r[2], r[3]);
            }
        }

        // ---- online softmax in exp2 domain; register P ----
        uint32_t pf[8][2];
        {
            float mx0 = -1e30f, mx1 = -1e30f;
            #pragma unroll
            for (int nt = 0; nt < 8; ++nt) {
                sacc[nt][0] *= rsc0; sacc[nt][1] *= rsc0;
                sacc[nt][2] *= rsc1; sacc[nt][3] *= rsc1;
                mx0 = fmaxf(mx0, fmaxf(sacc[nt][0], sacc[nt][1]));
                mx1 = fmaxf(mx1, fmaxf(sacc[nt][2], sacc[nt][3]));
            }
            mx0 = fmaxf(mx0, __shfl_xor_sync(0xffffffffu, mx0, 1));
            mx0 = fmaxf(mx0, __shfl_xor_sync(0xffffffffu, mx0, 2));
            mx1 = fmaxf(mx1, __shfl_xor_sync(0xffffffffu, mx1, 1));
            mx1 = fmaxf(mx1, __shfl_xor_sync(0xffffffffu, mx1, 2));

            const float mn0 = fmaxf(m0, mx0), mn1 = fmaxf(m1, mx1);
            const float cf0 = ex2f(m0 - mn0), cf1 = ex2f(m1 - mn1);
            float rs0 = 0.0f, rs1 = 0.0f;

            #pragma unroll
            for (int nt = 0; nt < 8; ++nt) {
                float p0 = ex2f(sacc[nt][0] - mn0);
                float p1 = ex2f(sacc[nt][1] - mn0);
                float p2 = ex2f(sacc[nt][2] - mn1);
                float p3 = ex2f(sacc[nt][3] - mn1);
                rs0 += p0 + p1;
                rs1 += p2 + p3;
                pf[nt][0] = packh2(p0, p1);
                pf[nt][1] = packh2(p2, p3);
            }
            rs0 += __shfl_xor_sync(0xffffffffu, rs0, 1);
            rs0 += __shfl_xor_sync(0xffffffffu, rs0, 2);
            rs1 += __shfl_xor_sync(0xffffffffu, rs1, 1);
            rs1 += __shfl_xor_sync(0xffffffffu, rs1, 2);

            m0 = mn0; l0 = l0 * cf0 + rs0;
            m1 = mn1; l1 = l1 * cf1 + rs1;
            // skip rescale when both maxes unchanged (cf == 1.0 exactly)
            if (cf0 < 1.0f || cf1 < 1.0f) {
                #pragma unroll
                for (int nt = 0; nt < 8; ++nt) {
                    oacc[nt][0] *= cf0; oacc[nt][1] *= cf0;
                    oacc[nt][2] *= cf1; oacc[nt][3] *= cf1;
                }
            }
        }

        // ---- O += P V : ldsm_x4.trans serves two dh-tiles at once ----
        #pragma unroll
        for (int ks = 0; ks < 4; ++ks) {
            uint32_t af[4];
            af[0] = pf[2 * ks][0];
            af[1] = pf[2 * ks][1];
            af[2] = pf[2 * ks + 1][0];
            af[3] = pf[2 * ks + 1][1];
            #pragma unroll
            for (int nt = 0; nt < 8; nt += 2) {
                uint32_t r[4];
                ldsm_x4t(VhB + (uint32_t)((ks * 16 * KSTRH + nt * 8) * 2) + voff4, r);
                mma_f16(oacc[nt],     af, r[0], r[1]);
                mma_f16(oacc[nt + 1], af, r[2], r[3]);
            }
        }
    }

    const float inv0 = 1.0f / l0, inv1 = 1.0f / l1;
    __half* op0 = ctx + qrow * D_M + h * DH;
    __half* op1 = op0 + (size_t)8 * D_M;
    #pragma unroll
    for (int nt = 0; nt < 8; ++nt) {
        const int col = nt * 8 + tg * 2;
        *(uint32_t*)(op0 + col) = packh2(oacc[nt][0] * inv0, oacc[nt][1] * inv0);
        *(uint32_t*)(op1 + col) = packh2(oacc[nt][2] * inv1, oacc[nt][3] * inv1);
    }
}

// ---------------------------------------------------------------------------
// Launch
// ---------------------------------------------------------------------------
extern "C" void kernel_launch(void* const* d_in, const int* in_sizes, int n_in,
                              void* d_out, int out_size)
{
    (void)in_sizes; (void)n_in; (void)out_size;

    const float* query = (const float*)d_in[0];
    const int*   mask  = (const int*)  d_in[1];
    const float* Wq    = (const float*)d_in[2];
    const float* bq    = (const float*)d_in[3];
    const float* Wk    = (const float*)d_in[4];
    const float* bk    = (const float*)d_in[5];
    const float* Wv    = (const float*)d_in[6];
    const float* bv    = (const float*)d_in[7];
    const float* Wo    = (const float*)d_in[8];
    const float* bo    = (const float*)d_in[9];
    float* out = (float*)d_out;

    __half *qh, *Qh, *Kh, *Vh, *ctxh, *Wqh, *Wkh, *Wvh, *Woh;
    cudaGetSymbolAddress((void**)&qh,   g_qh);
    cudaGetSymbolAddress((void**)&Qh,   g_Qh);
    cudaGetSymbolAddress((void**)&Kh,   g_Kh);
    cudaGetSymbolAddress((void**)&Vh,   g_Vh);
    cudaGetSymbolAddress((void**)&ctxh, g_ctxh);
    cudaGetSymbolAddress((void**)&Wqh,  g_Wqh);
    cudaGetSymbolAddress((void**)&Wkh,  g_Wkh);
    cudaGetSymbolAddress((void**)&Wvh,  g_Wvh);
    cudaGetSymbolAddress((void**)&Woh,  g_Woh);

    cudaFuncSetAttribute(hgemm_qkv,
                         cudaFuncAttributeMaxDynamicSharedMemorySize,
                         GEMM_SMEM_BYTES);
    cudaFuncSetAttribute(hgemm_out,
                         cudaFuncAttributeMaxDynamicSharedMemorySize,
                         GEMM_SMEM_BYTES);
    cudaFuncSetAttribute(flash_attn_f16,
                         cudaFuncAttributeMaxDynamicSharedMemorySize,
                         FA_SMEM_BYTES);

    const int nQ = MROWS * D_M;
    const int nW = D_M * D_M;
    cvt_f32_f16<<<nQ / 8 / 256, 256>>>(query, qh, nQ);
    cvt_weights<<<dim3(nW / 8 / 256, 4), 256>>>(Wq, Wk, Wv, Wo,
                                                Wqh, Wkh, Wvh, Woh);

    hgemm_qkv<<<dim3(D_M / 128, MROWS / 128, 3), 256, GEMM_SMEM_BYTES>>>(
        qh, Wqh, Wkh, Wvh, bq, bk, bv, Qh, Kh, Vh);

    flash_attn_f16<<<dim3(T_S / 128, H_N, N_B), 256, FA_SMEM_BYTES>>>(
        Qh, Kh, Vh, mask, ctxh);

    hgemm_out<<<dim3(D_M / 128, MROWS / 128), 256, GEMM_SMEM_BYTES>>>(
        ctxh, Woh, bo, out);
}

// round 17
// speedup vs baseline: 1.0616x; 1.0136x over previous
#include <cuda_runtime.h>
#include <cuda_fp16.h>
#include <math.h>
#include <stdint.h>

// Problem constants
#define N_B   4
#define T_S   2048
#define D_M   1024
#define H_N   16
#define DH    64
#define MROWS (N_B * T_S)   // 8192
#define GK    1024          // GEMM K

// ---------------------------------------------------------------------------
// Scratch (alloc-free rule: __device__ globals) — all f16
// ---------------------------------------------------------------------------
__device__ __half g_qh  [(size_t)MROWS * D_M];
__device__ __half g_Qh  [(size_t)MROWS * D_M];
__device__ __half g_Kh  [(size_t)MROWS * D_M];
__device__ __half g_Vh  [(size_t)MROWS * D_M];
__device__ __half g_ctxh[(size_t)MROWS * D_M];
__device__ __half g_Wqh [(size_t)D_M * D_M];
__device__ __half g_Wkh [(size_t)D_M * D_M];
__device__ __half g_Wvh [(size_t)D_M * D_M];
__device__ __half g_Woh [(size_t)D_M * D_M];

// ---------------------------------------------------------------------------
// Helpers (sm_100 plain target: NO tcgen05)
// ---------------------------------------------------------------------------
__device__ __forceinline__ uint32_t smem_to_u32(const void* p) {
    uint32_t a;
    asm("{ .reg .u64 t; cvta.to.shared.u64 t, %1; cvt.u32.u64 %0, t; }"
        : "=r"(a) : "l"(p));
    return a;
}
__device__ __forceinline__ void cpa16(uint32_t dst, const void* src) {
    asm volatile("cp.async.cg.shared.global [%0], [%1], 16;"
                 :: "r"(dst), "l"(src) : "memory");
}
#define CP_COMMIT() asm volatile("cp.async.commit_group;" ::: "memory")

__device__ __forceinline__ uint32_t packh2(float lo, float hi) {
    __half2 h = __floats2half2_rn(lo, hi);
    return *(uint32_t*)&h;
}
__device__ __forceinline__ float ex2f(float x) {
    float y;
    asm("ex2.approx.f32 %0, %1;" : "=f"(y) : "f"(x));
    return y;
}
// D(16x8,f32) += A(16x16,f16 row) * B(16x8,f16 col)
__device__ __forceinline__ void mma_f16(float* d, const uint32_t* a,
                                        uint32_t b0, uint32_t b1) {
    asm volatile(
        "mma.sync.aligned.m16n8k16.row.col.f32.f16.f16.f32 "
        "{%0,%1,%2,%3}, {%4,%5,%6,%7}, {%8,%9}, {%0,%1,%2,%3};"
        : "+f"(d[0]), "+f"(d[1]), "+f"(d[2]), "+f"(d[3])
        : "r"(a[0]), "r"(a[1]), "r"(a[2]), "r"(a[3]),
          "r"(b0), "r"(b1));
}
__device__ __forceinline__ void ldsm_x2(uint32_t addr, uint32_t& r0, uint32_t& r1) {
    asm volatile("ldmatrix.sync.aligned.m8n8.x2.shared.b16 {%0,%1}, [%2];"
                 : "=r"(r0), "=r"(r1) : "r"(addr));
}
__device__ __forceinline__ void ldsm_x2t(uint32_t addr, uint32_t& r0, uint32_t& r1) {
    asm volatile("ldmatrix.sync.aligned.m8n8.x2.trans.shared.b16 {%0,%1}, [%2];"
                 : "=r"(r0), "=r"(r1) : "r"(addr));
}
__device__ __forceinline__ void ldsm_x4(uint32_t addr, uint32_t* r) {
    asm volatile("ldmatrix.sync.aligned.m8n8.x4.shared.b16 {%0,%1,%2,%3}, [%4];"
                 : "=r"(r[0]), "=r"(r[1]), "=r"(r[2]), "=r"(r[3]) : "r"(addr));
}

// ---------------------------------------------------------------------------
// fp32 -> fp16 converts
// ---------------------------------------------------------------------------
__global__ void cvt_f32_f16(const float* __restrict__ in,
                            __half* __restrict__ out, int n)
{
    int i = (blockIdx.x * blockDim.x + threadIdx.x) * 8;
    if (i >= n) return;
    float4 a = *(const float4*)(in + i);
    float4 b = *(const float4*)(in + i + 4);
    uint4 o;
    o.x = packh2(a.x, a.y); o.y = packh2(a.z, a.w);
    o.z = packh2(b.x, b.y); o.w = packh2(b.z, b.w);
    *(uint4*)(out + i) = o;
}

__global__ void cvt_weights(const float* w0, const float* w1,
                            const float* w2, const float* w3,
                            __half* o0, __half* o1, __half* o2, __half* o3)
{
    const float* src[4] = {w0, w1, w2, w3};
    __half*      dst[4] = {o0, o1, o2, o3};
    const float* in  = src[blockIdx.y];
    __half*      out = dst[blockIdx.y];
    int i = (blockIdx.x * blockDim.x + threadIdx.x) * 8;
    float4 a = *(const float4*)(in + i);
    float4 b = *(const float4*)(in + i + 4);
    uint4 o;
    o.x = packh2(a.x, a.y); o.y = packh2(a.z, a.w);
    o.z = packh2(b.x, b.y); o.w = packh2(b.z, b.w);
    *(uint4*)(out + i) = o;
}

// ---------------------------------------------------------------------------
// FP16 GEMM core — R15 version unchanged (measured improvement).
// BK=64, 2-stage cp.async, one barrier per k-tile, B via ldsm_x4.
// ---------------------------------------------------------------------------
#define GSTR   72
#define GTILEB (128 * GSTR * 2)
#define GEMM_SMEM_BYTES (4 * GTILEB)

template<typename OutT>
__device__ __forceinline__ void hgemm_core(
    const __half* __restrict__ A, const __half* __restrict__ B,
    const float* __restrict__ bias, OutT* __restrict__ C,
    char* smc, int m0, int n0)
{
    const uint32_t sb = smem_to_u32(smc);
    const int tid  = threadIdx.x;
    const int wid  = tid >> 5;
    const int lane = tid & 31;
    const int g    = lane >> 2;
    const int tg   = lane & 3;
    const int warp_m = wid & 1;
    const int warp_n = wid >> 1;

    const int lr = tid >> 1;
    const int lc = (tid & 1) * 32;
    const __half* Ag = A + (size_t)(m0 + lr) * GK + lc;
    const __half* Bg = B + (size_t)(n0 + lr) * GK + lc;
    const uint32_t sdst = (uint32_t)(lr * (GSTR * 2) + lc * 2);

    const uint32_t aoff  = (uint32_t)(((lane & 15) * GSTR + (lane >> 4) * 8) * 2);
    const uint32_t boff4 = (uint32_t)((((lane & 7) + ((lane >> 4) << 3)) * GSTR) * 2
                                      + ((lane >> 3) & 1) * 16);

    #pragma unroll
    for (int j = 0; j < 4; ++j) {
        cpa16(sb + sdst + j * 16,              Ag + j * 8);
        cpa16(sb + 2 * GTILEB + sdst + j * 16, Bg + j * 8);
    }
    CP_COMMIT();

    float acc[4][4][4];
    #pragma unroll
    for (int mt = 0; mt < 4; ++mt)
        #pragma unroll
        for (int nt = 0; nt < 4; ++nt)
            #pragma unroll
            for (int u = 0; u < 4; ++u) acc[mt][nt][u] = 0.0f;

    const int NT = GK / 64;
    for (int kt = 0; kt < NT; ++kt) {
        const int buf = kt & 1;
        asm volatile("cp.async.wait_group 0;" ::: "memory");
        __syncthreads();

        if (kt + 1 < NT) {
            const int nb = buf ^ 1;
            const __half* Ag2 = Ag + (kt + 1) * 64;
            const __half* Bg2 = Bg + (kt + 1) * 64;
            #pragma unroll
            for (int j = 0; j < 4; ++j) {
                cpa16(sb + nb * GTILEB + sdst + j * 16,       Ag2 + j * 8);
                cpa16(sb + (2 + nb) * GTILEB + sdst + j * 16, Bg2 + j * 8);
            }
            CP_COMMIT();
        }

        const uint32_t AB = sb + buf * GTILEB;
        const uint32_t BB = sb + (2 + buf) * GTILEB;

        #pragma unroll
        for (int ks = 0; ks < 4; ++ks) {
            uint32_t af[4][4], bf[2][4];
            #pragma unroll
            for (int mt = 0; mt < 4; ++mt)
                ldsm_x4(AB + (uint32_t)((warp_m * 64 + mt * 16) * GSTR * 2 + ks * 32)
                           + aoff, af[mt]);
            #pragma unroll
            for (int ntp = 0; ntp < 2; ++ntp)
                ldsm_x4(BB + (uint32_t)((warp_n * 32 + ntp * 16) * GSTR * 2 + ks * 32)
                           + boff4, bf[ntp]);
            #pragma unroll
            for (int mt = 0; mt < 4; ++mt) {
                #pragma unroll
                for (int ntp = 0; ntp < 2; ++ntp) {
                    mma_f16(acc[mt][2 * ntp],     af[mt], bf[ntp][0], bf[ntp][1]);
                    mma_f16(acc[mt][2 * ntp + 1], af[mt], bf[ntp][2], bf[ntp][3]);
                }
            }
        }
    }

    #pragma unroll
    for (int nt = 0; nt < 4; ++nt) {
        const int col = n0 + warp_n * 32 + nt * 8 + tg * 2;
        const float b0 = bias[col], b1 = bias[col + 1];
        #pragma unroll
        for (int mt = 0; mt < 4; ++mt) {
            const int row = m0 + warp_m * 64 + mt * 16 + g;
            if (sizeof(OutT) == 2) {
                __half* Ch = (__half*)C;
                *(uint32_t*)(Ch + (size_t)row * D_M + col) =
                    packh2(acc[mt][nt][0] + b0, acc[mt][nt][1] + b1);
                *(uint32_t*)(Ch + (size_t)(row + 8) * D_M + col) =
                    packh2(acc[mt][nt][2] + b0, acc[mt][nt][3] + b1);
            } else {
                float* Cf = (float*)C;
                *(float2*)(Cf + (size_t)row * D_M + col) =
                    make_float2(acc[mt][nt][0] + b0, acc[mt][nt][1] + b1);
                *(float2*)(Cf + (size_t)(row + 8) * D_M + col) =
                    make_float2(acc[mt][nt][2] + b0, acc[mt][nt][3] + b1);
            }
        }
    }
}

__global__ __launch_bounds__(256, 2)
void hgemm_qkv(const __half* __restrict__ A,
               const __half* B0, const __half* B1, const __half* B2,
               const float* bias0, const float* bias1, const float* bias2,
               __half* C0, __half* C1, __half* C2)
{
    extern __shared__ char smc[];
    const __half* Bsel[3]    = {B0, B1, B2};
    const float*  biassel[3] = {bias0, bias1, bias2};
    __half*       Csel[3]    = {C0, C1, C2};
    const int z = blockIdx.z;
    hgemm_core<__half>(A, Bsel[z], biassel[z], Csel[z], smc,
                       blockIdx.y * 128, blockIdx.x * 128);
}

__global__ __launch_bounds__(256, 2)
void hgemm_out(const __half* __restrict__ A, const __half* __restrict__ B,
               const float* __restrict__ bias, float* __restrict__ C)
{
    extern __shared__ char smc[];
    hgemm_core<float>(A, B, bias, C, smc, blockIdx.y * 128, blockIdx.x * 128);
}

// ---------------------------------------------------------------------------
// Flash attention — exact R14 structure (measured best, 265 us: ldsm_x2/x2t
// fragments, UNCONDITIONAL rescale) + exp2-domain softmax only.
// ---------------------------------------------------------------------------
#define SK    64
#define KSTRH 72
#define KVTB  (SK * KSTRH * 2)
#define OFF_VH (2 * KVTB)
#define FA_SMEM_BYTES (4 * KVTB)      // 36864 B

#define LOG2E 1.4426950408889634f

__global__ __launch_bounds__(256, 2)
void flash_attn_f16(const __half* __restrict__ Q, const __half* __restrict__ K,
                    const __half* __restrict__ V, const int* __restrict__ mask,
                    __half* __restrict__ ctx)
{
    extern __shared__ char smc[];
    const uint32_t sb = smem_to_u32(smc);

    const int tid  = threadIdx.x;
    const int wid  = tid >> 5;
    const int lane = tid & 31;
    const int g    = lane >> 2;
    const int tg   = lane & 3;
    const int t0 = blockIdx.x * 128;
    const int h  = blockIdx.y;
    const int n  = blockIdx.z;

    const size_t qrow = (size_t)(n * T_S + t0 + wid * 16 + g);
    const __half* Qp0 = Q + qrow * D_M + h * DH;
    const __half* Qp1 = Qp0 + (size_t)8 * D_M;
    uint32_t qf[4][4];
    #pragma unroll
    for (int ks = 0; ks < 4; ++ks) {
        const int c = ks * 16 + 2 * tg;
        qf[ks][0] = *(const uint32_t*)(Qp0 + c);
        qf[ks][1] = *(const uint32_t*)(Qp1 + c);
        qf[ks][2] = *(const uint32_t*)(Qp0 + c + 8);
        qf[ks][3] = *(const uint32_t*)(Qp1 + c + 8);
    }

    // exp2-domain: fold log2(e) into the row scale once.
    const float rsc0 = (mask[n * T_S + t0 + wid * 16 + g]     != 0) ? 0.125f * LOG2E : 0.0f;
    const float rsc1 = (mask[n * T_S + t0 + wid * 16 + g + 8] != 0) ? 0.125f * LOG2E : 0.0f;

    float m0 = -1e30f, l0 = 0.0f, m1 = -1e30f, l1 = 0.0f;
    float oacc[8][4];
    #pragma unroll
    for (int nt = 0; nt < 8; ++nt)
        #pragma unroll
        for (int u = 0; u < 4; ++u) oacc[nt][u] = 0.0f;

    const int cr = tid >> 2;
    const int cq = (tid & 3) * 16;
    const __half* Kg = K + ((size_t)(n * T_S) + cr) * D_M + h * DH + cq;
    const __half* Vg = V + ((size_t)(n * T_S) + cr) * D_M + h * DH + cq;
    const uint32_t cdst = (uint32_t)(cr * (KSTRH * 2) + cq * 2);

    const uint32_t koff = (uint32_t)(((lane & 7) * KSTRH + ((lane >> 3) & 1) * 8) * 2);
    const uint32_t voff = (uint32_t)((lane & 15) * KSTRH * 2);

    cpa16(sb + cdst,               Kg);
    cpa16(sb + cdst + 16,          Kg + 8);
    cpa16(sb + OFF_VH + cdst,      Vg);
    cpa16(sb + OFF_VH + cdst + 16, Vg + 8);
    CP_COMMIT();

    const int NST = T_S / SK;   // 32
    for (int st = 0; st < NST; ++st) {
        const int buf = st & 1;
        asm volatile("cp.async.wait_group 0;" ::: "memory");
        __syncthreads();

        if (st + 1 < NST) {
            const int nb = buf ^ 1;
            const size_t go = (size_t)(st + 1) * SK * D_M;
            cpa16(sb + nb * KVTB + cdst,               Kg + go);
            cpa16(sb + nb * KVTB + cdst + 16,          Kg + go + 8);
            cpa16(sb + OFF_VH + nb * KVTB + cdst,      Vg + go);
            cpa16(sb + OFF_VH + nb * KVTB + cdst + 16, Vg + go + 8);
            CP_COMMIT();
        }

        const uint32_t KhB = sb + buf * KVTB;
        const uint32_t VhB = sb + OFF_VH + buf * KVTB;

        float sacc[8][4];
        #pragma unroll
        for (int nt = 0; nt < 8; ++nt)
            #pragma unroll
            for (int u = 0; u < 4; ++u) sacc[nt][u] = 0.0f;

        #pragma unroll
        for (int ks = 0; ks < 4; ++ks) {
            #pragma unroll
            for (int nt = 0; nt < 8; ++nt) {
                uint32_t b0, b1;
                ldsm_x2(KhB + (uint32_t)((nt * 8 * KSTRH + ks * 16) * 2) + koff, b0, b1);
                mma_f16(sacc[nt], qf[ks], b0, b1);
            }
        }

        uint32_t pf[8][2];
        {
            float mx0 = -1e30f, mx1 = -1e30f;
            #pragma unroll
            for (int nt = 0; nt < 8; ++nt) {
                sacc[nt][0] *= rsc0; sacc[nt][1] *= rsc0;
                sacc[nt][2] *= rsc1; sacc[nt][3] *= rsc1;
                mx0 = fmaxf(mx0, fmaxf(sacc[nt][0], sacc[nt][1]));
                mx1 = fmaxf(mx1, fmaxf(sacc[nt][2], sacc[nt][3]));
            }
            mx0 = fmaxf(mx0, __shfl_xor_sync(0xffffffffu, mx0, 1));
            mx0 = fmaxf(mx0, __shfl_xor_sync(0xffffffffu, mx0, 2));
            mx1 = fmaxf(mx1, __shfl_xor_sync(0xffffffffu, mx1, 1));
            mx1 = fmaxf(mx1, __shfl_xor_sync(0xffffffffu, mx1, 2));

            const float mn0 = fmaxf(m0, mx0), mn1 = fmaxf(m1, mx1);
            const float cf0 = ex2f(m0 - mn0), cf1 = ex2f(m1 - mn1);
            float rs0 = 0.0f, rs1 = 0.0f;

            #pragma unroll
            for (int nt = 0; nt < 8; ++nt) {
                float p0 = ex2f(sacc[nt][0] - mn0);
                float p1 = ex2f(sacc[nt][1] - mn0);
                float p2 = ex2f(sacc[nt][2] - mn1);
                float p3 = ex2f(sacc[nt][3] - mn1);
                rs0 += p0 + p1;
                rs1 += p2 + p3;
                pf[nt][0] = packh2(p0, p1);
                pf[nt][1] = packh2(p2, p3);
            }
            rs0 += __shfl_xor_sync(0xffffffffu, rs0, 1);
            rs0 += __shfl_xor_sync(0xffffffffu, rs0, 2);
            rs1 += __shfl_xor_sync(0xffffffffu, rs1, 1);
            rs1 += __shfl_xor_sync(0xffffffffu, rs1, 2);

            m0 = mn0; l0 = l0 * cf0 + rs0;
            m1 = mn1; l1 = l1 * cf1 + rs1;
            #pragma unroll
            for (int nt = 0; nt < 8; ++nt) {
                oacc[nt][0] *= cf0; oacc[nt][1] *= cf0;
                oacc[nt][2] *= cf1; oacc[nt][3] *= cf1;
            }
        }

        #pragma unroll
        for (int ks = 0; ks < 4; ++ks) {
            uint32_t af[4];
            af[0] = pf[2 * ks][0];
            af[1] = pf[2 * ks][1];
            af[2] = pf[2 * ks + 1][0];
            af[3] = pf[2 * ks + 1][1];
            #pragma unroll
            for (int nt = 0; nt < 8; ++nt) {
                uint32_t b0, b1;
                ldsm_x2t(VhB + (uint32_t)((ks * 16 * KSTRH + nt * 8) * 2) + voff, b0, b1);
                mma_f16(oacc[nt], af, b0, b1);
            }
        }
    }

    const float inv0 = 1.0f / l0, inv1 = 1.0f / l1;
    __half* op0 = ctx + qrow * D_M + h * DH;
    __half* op1 = op0 + (size_t)8 * D_M;
    #pragma unroll
    for (int nt = 0; nt < 8; ++nt) {
        const int col = nt * 8 + tg * 2;
        *(uint32_t*)(op0 + col) = packh2(oacc[nt][0] * inv0, oacc[nt][1] * inv0);
        *(uint32_t*)(op1 + col) = packh2(oacc[nt][2] * inv1, oacc[nt][3] * inv1);
    }
}

// ---------------------------------------------------------------------------
// Launch
// ---------------------------------------------------------------------------
extern "C" void kernel_launch(void* const* d_in, const int* in_sizes, int n_in,
                              void* d_out, int out_size)
{
    (void)in_sizes; (void)n_in; (void)out_size;

    const float* query = (const float*)d_in[0];
    const int*   mask  = (const int*)  d_in[1];
    const float* Wq    = (const float*)d_in[2];
    const float* bq    = (const float*)d_in[3];
    const float* Wk    = (const float*)d_in[4];
    const float* bk    = (const float*)d_in[5];
    const float* Wv    = (const float*)d_in[6];
    const float* bv    = (const float*)d_in[7];
    const float* Wo    = (const float*)d_in[8];
    const float* bo    = (const float*)d_in[9];
    float* out = (float*)d_out;

    __half *qh, *Qh, *Kh, *Vh, *ctxh, *Wqh, *Wkh, *Wvh, *Woh;
    cudaGetSymbolAddress((void**)&qh,   g_qh);
    cudaGetSymbolAddress((void**)&Qh,   g_Qh);
    cudaGetSymbolAddress((void**)&Kh,   g_Kh);
    cudaGetSymbolAddress((void**)&Vh,   g_Vh);
    cudaGetSymbolAddress((void**)&ctxh, g_ctxh);
    cudaGetSymbolAddress((void**)&Wqh,  g_Wqh);
    cudaGetSymbolAddress((void**)&Wkh,  g_Wkh);
    cudaGetSymbolAddress((void**)&Wvh,  g_Wvh);
    cudaGetSymbolAddress((void**)&Woh,  g_Woh);

    cudaFuncSetAttribute(hgemm_qkv,
                         cudaFuncAttributeMaxDynamicSharedMemorySize,
                         GEMM_SMEM_BYTES);
    cudaFuncSetAttribute(hgemm_out,
                         cudaFuncAttributeMaxDynamicSharedMemorySize,
                         GEMM_SMEM_BYTES);
    cudaFuncSetAttribute(flash_attn_f16,
                         cudaFuncAttributeMaxDynamicSharedMemorySize,
                         FA_SMEM_BYTES);

    const int nQ = MROWS * D_M;
    const int nW = D_M * D_M;
    cvt_f32_f16<<<nQ / 8 / 256, 256>>>(query, qh, nQ);
    cvt_weights<<<dim3(nW / 8 / 256, 4), 256>>>(Wq, Wk, Wv, Wo,
                                                Wqh, Wkh, Wvh, Woh);

    hgemm_qkv<<<dim3(D_M / 128, MROWS / 128, 3), 256, GEMM_SMEM_BYTES>>>(
        qh, Wqh, Wkh, Wvh, bq, bk, bv, Qh, Kh, Vh);

    flash_attn_f16<<<dim3(T_S / 128, H_N, N_B), 256, FA_SMEM_BYTES>>>(
        Qh, Kh, Vh, mask, ctxh);

    hgemm_out<<<dim3(D_M / 128, MROWS / 128), 256, GEMM_SMEM_BYTES>>>(
        ctxh, Woh, bo, out);
}